// round 13
// baseline (speedup 1.0000x reference)
#include <cuda_runtime.h>

// Problem constants
#define CELLS 64              // B*S = 8*8
#define HW 262144             // 512*512
#define HW4 65536             // HW / 4 (float4 count per cell)
#define CHUNKS 16             // blocks per cell -> 1024 blocks total = ONE wave
#define THREADS 256
#define F4_PER_THREAD 16      // 16*256*16 = 65536 = HW4

// Tiny per-cell accumulators (padded rows for vector access).
// Zero at module load; each replay: reduce_kernel atomically accumulates,
// final_kernel reads then resets. Deterministic under stream ordering.
__device__ __align__(32) float g_acc[CELLS][8];

__global__ void __launch_bounds__(THREADS) reduce_kernel(
    const float4* __restrict__ probs,     // seg_probs
    const float4* __restrict__ targs,     // seg_targets (0/1)
    const float4* __restrict__ attn)      // attention_maps
{
    const int cell  = blockIdx.y;
    const int chunk = blockIdx.x;
    long base = (long)cell * HW4 + (long)chunk * (THREADS * F4_PER_THREAD) + threadIdx.x;

    float s_bce = 0.f, s_foc = 0.f, s_ptv = 0.f, s_p = 0.f, s_t = 0.f, s_att = 0.f;

#pragma unroll
    for (int it = 0; it < F4_PER_THREAD; it++) {
        long idx = base + (long)it * THREADS;
        float4 p = probs[idx];
        float4 t = targs[idx];
        float4 a = attn[idx];

        const float* pv = &p.x;
        const float* tv = &t.x;
        const float* av = &a.x;
#pragma unroll
        for (int k = 0; k < 4; k++) {
            float pk = pv[k], tk = tv[k], ak = av[k];
            // t in {0,1}:  pt_val = t ? p : (1-p) = 1 - p - t + 2pt = exp(-bce)
            float ptval = fmaf(2.f * pk, tk, 1.f - pk - tk);
            float l = __logf(ptval);            // bce = -l
            s_bce -= l;
            float om = 1.f - ptval;
            s_foc -= om * om * l;               // (1-pt)^2 * bce (alpha folded later)
            s_ptv = fmaf(pk, tk, s_ptv);
            s_p  += pk;
            s_t  += tk;
            // attention BCE with target==t: -log(t ? a : 1-a)
            float aval = fmaf(2.f * ak, tk, 1.f - ak - tk);
            s_att -= __logf(aval);
        }
    }

    // warp reduce the 6 sums
    float s[6] = {s_bce, s_foc, s_ptv, s_p, s_t, s_att};
#pragma unroll
    for (int j = 0; j < 6; j++) {
#pragma unroll
        for (int off = 16; off > 0; off >>= 1)
            s[j] += __shfl_xor_sync(0xffffffffu, s[j], off);
    }

    __shared__ float sh[THREADS / 32][6];
    int warp = threadIdx.x >> 5, lane = threadIdx.x & 31;
    if (lane == 0) {
#pragma unroll
        for (int j = 0; j < 6; j++) sh[warp][j] = s[j];
    }
    __syncthreads();
    if (threadIdx.x < 6) {
        float v = 0.f;
#pragma unroll
        for (int w = 0; w < THREADS / 32; w++) v += sh[w][threadIdx.x];
        atomicAdd(&g_acc[cell][threadIdx.x], v);
    }
}

__global__ void __launch_bounds__(64) final_kernel(
    const float* __restrict__ presence_probs,
    const int*   __restrict__ presence_targets,
    float*       __restrict__ out)
{
    const int c = threadIdx.x;          // 0..63, one cell per thread
    const int warp = c >> 5, lane = c & 31;

    // Read accumulators (L2-resident from atomics; bypass L1), then reset.
    float4 v0 = __ldcg((const float4*)&g_acc[c][0]);
    float2 v1 = __ldcg((const float2*)&g_acc[c][4]);
    float4 z4 = make_float4(0.f, 0.f, 0.f, 0.f);
    *(float4*)&g_acc[c][0] = z4;
    *(float4*)&g_acc[c][4] = z4;

    float sb  = v0.x;   // bce sum
    float sf  = v0.y;   // focal raw sum
    float spt = v0.z;   // p*t
    float sp  = v0.w;   // p
    float st  = v1.x;   // t
    float sa  = v1.y;   // att bce sum

    float pres = (float)presence_targets[c];
    float pp   = presence_probs[c];

    const float inv_hw = 1.0f / (float)HW;
    float bce_mean   = sb * inv_hw;
    float focal_mean = 0.25f * sf * inv_hw;   // FOCAL_ALPHA
    float dice       = 1.f - (2.f * spt + 1e-6f) / (sp + st + 1e-6f);
    float att_mean   = sa * inv_hw;

    // absence BCE (pp in (1e-4, 1-1e-4): reference clamps inert)
    float absence = -(pres * logf(pp) + (1.f - pres) * logf(1.f - pp));

    bool wrong = ((pres == 0.f) && (pp > 0.5f)) || ((pres == 1.f) && (pp < 0.5f));
    float d = pp - 0.5f;
    float conf = wrong ? d * d : 0.f;

    float term[7];
    term[0] = pres;
    term[1] = bce_mean   * pres;
    term[2] = dice       * pres;
    term[3] = focal_mean * pres;
    term[4] = absence;
    term[5] = att_mean   * pres;
    term[6] = conf;

    // Shuffle-reduce the 7 terms within each warp, combine the 2 warps in smem.
#pragma unroll
    for (int j = 0; j < 7; j++) {
#pragma unroll
        for (int off = 16; off > 0; off >>= 1)
            term[j] += __shfl_xor_sync(0xffffffffu, term[j], off);
    }
    __shared__ float sh_fin[2][7];
    if (lane == 0) {
#pragma unroll
        for (int j = 0; j < 7; j++) sh_fin[warp][j] = term[j];
    }
    __syncthreads();

    if (threadIdx.x == 0) {
        float cnt   = sh_fin[0][0] + sh_fin[1][0];
        float Sseg  = sh_fin[0][1] + sh_fin[1][1];
        float Sdice = sh_fin[0][2] + sh_fin[1][2];
        float Sfoc  = sh_fin[0][3] + sh_fin[1][3];
        float Sabs  = sh_fin[0][4] + sh_fin[1][4];
        float Satt  = sh_fin[0][5] + sh_fin[1][5];
        float Sconf = sh_fin[0][6] + sh_fin[1][6];

        float safe = fmaxf(cnt, 1.f);
        float seg_loss   = (cnt > 0.f) ? Sseg  / safe : 0.f;
        float dice_loss  = (cnt > 0.f) ? Sdice / safe : 0.f;
        float focal_loss = (cnt > 0.f) ? Sfoc  / safe : 0.f;
        float n_cells = (float)CELLS;

        out[0] = 1.0f * seg_loss
               + 1.0f * dice_loss
               + 0.5f * focal_loss
               + 1.0f * (Sabs / n_cells)
               + 0.5f * (Satt / n_cells)
               + 0.1f * (Sconf / n_cells);
    }
}

extern "C" void kernel_launch(void* const* d_in, const int* in_sizes, int n_in,
                              void* d_out, int out_size)
{
    // metadata order: seg_logits, seg_probs, seg_targets, presence_probs,
    //                 attention_maps, presence_targets
    // seg_logits (d_in[0]) is redundant: probs = sigmoid(logits) is given and
    // targets are exactly {0,1}, so bce = -log(t ? p : 1-p).
    const float4* probs = (const float4*)d_in[1];
    const float4* targs = (const float4*)d_in[2];
    const float*  pp    = (const float*)d_in[3];
    const float4* attn  = (const float4*)d_in[4];
    const int*    pt    = (const int*)d_in[5];
    float* out = (float*)d_out;

    dim3 grid(CHUNKS, CELLS);
    reduce_kernel<<<grid, THREADS>>>(probs, targs, attn);
    final_kernel<<<1, 64>>>(pp, pt, out);
}

// round 15
// speedup vs baseline: 1.0715x; 1.0715x over previous
#include <cuda_runtime.h>

// Problem constants
#define CELLS 64              // B*S = 8*8
#define HW 262144             // 512*512
#define HW4 65536             // HW / 4 (float4 count per cell)
#define CHUNKS 32             // blocks per cell (measured optimum)
#define THREADS 256
#define F4_PER_THREAD 8       // 32*256*8 = 65536 = HW4

// Tiny per-cell accumulators (padded rows for vector access).
// Zero at module load; each replay: reduce_kernel atomically accumulates,
// final_kernel reads then resets. Deterministic under stream ordering.
__device__ __align__(32) float g_acc[CELLS][8];

__global__ void __launch_bounds__(THREADS) reduce_kernel(
    const float4* __restrict__ probs,     // seg_probs
    const float4* __restrict__ targs,     // seg_targets (0/1)
    const float4* __restrict__ attn)      // attention_maps
{
    const int cell  = blockIdx.y;
    const int chunk = blockIdx.x;
    long base = (long)cell * HW4 + (long)chunk * (THREADS * F4_PER_THREAD) + threadIdx.x;

    float s_bce = 0.f, s_foc = 0.f, s_ptv = 0.f, s_p = 0.f, s_t = 0.f, s_att = 0.f;

#pragma unroll
    for (int it = 0; it < F4_PER_THREAD; it++) {
        long idx = base + (long)it * THREADS;
        float4 p = probs[idx];
        float4 t = targs[idx];
        float4 a = attn[idx];

        const float* pv = &p.x;
        const float* tv = &t.x;
        const float* av = &a.x;
#pragma unroll
        for (int k = 0; k < 4; k++) {
            float pk = pv[k], tk = tv[k], ak = av[k];
            // t in {0,1}:  pt_val = t ? p : (1-p) = 1 - p - t + 2pt = exp(-bce)
            float ptval = fmaf(2.f * pk, tk, 1.f - pk - tk);
            float l = __logf(ptval);            // bce = -l
            s_bce -= l;
            float om = 1.f - ptval;
            s_foc -= om * om * l;               // (1-pt)^2 * bce (alpha folded later)
            s_ptv = fmaf(pk, tk, s_ptv);
            s_p  += pk;
            s_t  += tk;
            // attention BCE with target==t: -log(t ? a : 1-a)
            float aval = fmaf(2.f * ak, tk, 1.f - ak - tk);
            s_att -= __logf(aval);
        }
    }

    // warp reduce the 6 sums
    float s[6] = {s_bce, s_foc, s_ptv, s_p, s_t, s_att};
#pragma unroll
    for (int j = 0; j < 6; j++) {
#pragma unroll
        for (int off = 16; off > 0; off >>= 1)
            s[j] += __shfl_xor_sync(0xffffffffu, s[j], off);
    }

    __shared__ float sh[THREADS / 32][6];
    int warp = threadIdx.x >> 5, lane = threadIdx.x & 31;
    if (lane == 0) {
#pragma unroll
        for (int j = 0; j < 6; j++) sh[warp][j] = s[j];
    }
    __syncthreads();
    if (threadIdx.x < 6) {
        float v = 0.f;
#pragma unroll
        for (int w = 0; w < THREADS / 32; w++) v += sh[w][threadIdx.x];
        atomicAdd(&g_acc[cell][threadIdx.x], v);
    }
}

__global__ void __launch_bounds__(64) final_kernel(
    const float* __restrict__ presence_probs,
    const int*   __restrict__ presence_targets,
    float*       __restrict__ out)
{
    const int c = threadIdx.x;          // 0..63, one cell per thread
    const int warp = c >> 5, lane = c & 31;

    // Read accumulators (L2-resident from atomics; bypass L1), then reset.
    float4 v0 = __ldcg((const float4*)&g_acc[c][0]);
    float2 v1 = __ldcg((const float2*)&g_acc[c][4]);
    float4 z4 = make_float4(0.f, 0.f, 0.f, 0.f);
    *(float4*)&g_acc[c][0] = z4;
    *(float4*)&g_acc[c][4] = z4;

    float sb  = v0.x;   // bce sum
    float sf  = v0.y;   // focal raw sum
    float spt = v0.z;   // p*t
    float sp  = v0.w;   // p
    float st  = v1.x;   // t
    float sa  = v1.y;   // att bce sum

    float pres = (float)presence_targets[c];
    float pp   = presence_probs[c];

    const float inv_hw = 1.0f / (float)HW;
    float bce_mean   = sb * inv_hw;
    float focal_mean = 0.25f * sf * inv_hw;   // FOCAL_ALPHA
    float dice       = 1.f - (2.f * spt + 1e-6f) / (sp + st + 1e-6f);
    float att_mean   = sa * inv_hw;

    // absence BCE (pp in (1e-4, 1-1e-4): reference clamps inert)
    float absence = -(pres * logf(pp) + (1.f - pres) * logf(1.f - pp));

    bool wrong = ((pres == 0.f) && (pp > 0.5f)) || ((pres == 1.f) && (pp < 0.5f));
    float d = pp - 0.5f;
    float conf = wrong ? d * d : 0.f;

    float term[7];
    term[0] = pres;
    term[1] = bce_mean   * pres;
    term[2] = dice       * pres;
    term[3] = focal_mean * pres;
    term[4] = absence;
    term[5] = att_mean   * pres;
    term[6] = conf;

    // Shuffle-reduce the 7 terms within each warp, combine the 2 warps in smem.
#pragma unroll
    for (int j = 0; j < 7; j++) {
#pragma unroll
        for (int off = 16; off > 0; off >>= 1)
            term[j] += __shfl_xor_sync(0xffffffffu, term[j], off);
    }
    __shared__ float sh_fin[2][7];
    if (lane == 0) {
#pragma unroll
        for (int j = 0; j < 7; j++) sh_fin[warp][j] = term[j];
    }
    __syncthreads();

    if (threadIdx.x == 0) {
        float cnt   = sh_fin[0][0] + sh_fin[1][0];
        float Sseg  = sh_fin[0][1] + sh_fin[1][1];
        float Sdice = sh_fin[0][2] + sh_fin[1][2];
        float Sfoc  = sh_fin[0][3] + sh_fin[1][3];
        float Sabs  = sh_fin[0][4] + sh_fin[1][4];
        float Satt  = sh_fin[0][5] + sh_fin[1][5];
        float Sconf = sh_fin[0][6] + sh_fin[1][6];

        float safe = fmaxf(cnt, 1.f);
        float seg_loss   = (cnt > 0.f) ? Sseg  / safe : 0.f;
        float dice_loss  = (cnt > 0.f) ? Sdice / safe : 0.f;
        float focal_loss = (cnt > 0.f) ? Sfoc  / safe : 0.f;
        float n_cells = (float)CELLS;

        out[0] = 1.0f * seg_loss
               + 1.0f * dice_loss
               + 0.5f * focal_loss
               + 1.0f * (Sabs / n_cells)
               + 0.5f * (Satt / n_cells)
               + 0.1f * (Sconf / n_cells);
    }
}

extern "C" void kernel_launch(void* const* d_in, const int* in_sizes, int n_in,
                              void* d_out, int out_size)
{
    // metadata order: seg_logits, seg_probs, seg_targets, presence_probs,
    //                 attention_maps, presence_targets
    // seg_logits (d_in[0]) is redundant: probs = sigmoid(logits) is given and
    // targets are exactly {0,1}, so bce = -log(t ? p : 1-p).
    const float4* probs = (const float4*)d_in[1];
    const float4* targs = (const float4*)d_in[2];
    const float*  pp    = (const float*)d_in[3];
    const float4* attn  = (const float4*)d_in[4];
    const int*    pt    = (const int*)d_in[5];
    float* out = (float*)d_out;

    dim3 grid(CHUNKS, CELLS);
    reduce_kernel<<<grid, THREADS>>>(probs, targs, attn);
    final_kernel<<<1, 64>>>(pp, pt, out);
}